// round 15
// baseline (speedup 1.0000x reference)
#include <cuda_runtime.h>
#include <cuda_fp16.h>

// Problem constants (fixed by the dataset)
#define F_IN 100
#define F_HID 100
#define F_EMB 64
#define N_CLS 40
#define NN   50000
#define EE   800000
#define CAP  96        // fixed slots per node; P(deg>=96) ~ 0 for Poisson(16)
#define PADH 128       // padded fp16 row stride for 100-wide activations (256B)
#define FILLB 296      // fill blocks fused into mega kernel (2 per SM)
#define XSTR 132       // transposed x-tile row stride (floats), 16B aligned

// ---------------- scratch (no allocations allowed) ----------------
__device__ __half g_Ah1[NN * PADH];    // layer1 lin output, fp16 UNSCALED, padded
__device__ __half g_Ah2[NN * F_EMB];   // layer2 lin output, fp16, dinv-scaled (128B rows)
__device__ float  g_B1[NN * F_HID];    // layer1 agg output (fp32, stride 100)
__device__ float  g_B2[NN * F_EMB];    // layer2 agg output (fp32, stride 64)
__device__ int    g_cnt[NN];           // cursor -> degree
__device__ int    g_col[NN * CAP];     // slot CSR (CAP multiple of 4 -> int4 aligned)
__device__ float  g_dinv[NN];

// ---------------- f32x2 packed helpers (sm_103a) ----------------
__device__ __forceinline__ unsigned long long pack2(float lo, float hi) {
    unsigned long long r;
    asm("mov.b64 %0, {%1, %2};" : "=l"(r) : "f"(lo), "f"(hi));
    return r;
}
__device__ __forceinline__ void ffma2(unsigned long long& d,
                                      unsigned long long a,
                                      unsigned long long b) {
    asm("fma.rn.f32x2 %0, %1, %2, %3;" : "=l"(d) : "l"(a), "l"(b), "l"(d));
}
__device__ __forceinline__ float2 unpack2(unsigned long long v) {
    float lo, hi;
    asm("mov.b64 {%0, %1}, %2;" : "=f"(lo), "=f"(hi) : "l"(v));
    return make_float2(lo, hi);
}

// 8 packed halves (uint4) -> fp32, fused multiply-add into acc[8] with scale dv
__device__ __forceinline__ void h8_fma(uint4 v, float dv, float* acc) {
    float2 f0 = __half22float2(*(const __half2*)&v.x);
    float2 f1 = __half22float2(*(const __half2*)&v.y);
    float2 f2 = __half22float2(*(const __half2*)&v.z);
    float2 f3 = __half22float2(*(const __half2*)&v.w);
    acc[0] = fmaf(f0.x, dv, acc[0]); acc[1] = fmaf(f0.y, dv, acc[1]);
    acc[2] = fmaf(f1.x, dv, acc[2]); acc[3] = fmaf(f1.y, dv, acc[3]);
    acc[4] = fmaf(f2.x, dv, acc[4]); acc[5] = fmaf(f2.y, dv, acc[5]);
    acc[6] = fmaf(f3.x, dv, acc[6]); acc[7] = fmaf(f3.y, dv, acc[7]);
}
__device__ __forceinline__ void h8_add(uint4 v, float* acc) { h8_fma(v, 1.0f, acc); }

// ---------------- single-stage full-K GEMM body ----------------
// out[n, * (stride OUTS)] = in[n, K (stride INS)] @ W[K, NOUT]
// Whole K staged in smem; ONE __syncthreads; straight-line k-loop.
// smem layout: xs = smem[0 .. K*XSTR), ws = smem[K*XSTR .. K*XSTR + K*NP)
template<int K, int NOUT, int NP, int INS, int OUTS, bool SCALE, bool BIAS, bool OUTH>
__device__ __forceinline__ void gemm_body(int bx,
                                          const float* __restrict__ in,
                                          const float* __restrict__ W,
                                          const float* __restrict__ bias,
                                          const float* __restrict__ dinv,
                                          float* __restrict__ outf,
                                          __half* __restrict__ outh, int n,
                                          float* smem) {
    constexpr int BM = 128, NJ = NP / 32;
    constexpr int KV4 = K / 4;                   // float4 per row (K % 4 == 0)
    float* xs = smem;                            // [K][XSTR] transposed
    float* ws = smem + K * XSTR;                 // [K][NP]
    const int tid = threadIdx.x;
    const int tx = tid & 31, ty = tid >> 5;      // 8 warps, 16 rows each
    const int rbase = bx * BM;

    // stage x tile: BM*KV4 float4 loads, coalesced within rows, transposed stores
    for (int idx = tid; idx < BM * KV4; idx += 256) {
        int row = idx / KV4;
        int c4  = idx - row * KV4;
        int grow = rbase + row;
        float4 xv = make_float4(0.f, 0.f, 0.f, 0.f);
        if (grow < n)
            xv = *(const float4*)(in + (size_t)grow * INS + c4 * 4);
        float* xp = xs + (c4 * 4) * XSTR + row;
        xp[0 * XSTR] = xv.x;
        xp[1 * XSTR] = xv.y;
        xp[2 * XSTR] = xv.z;
        xp[3 * XSTR] = xv.w;
    }
    // stage full W (zero padded columns)
    for (int i = tid; i < K * NP; i += 256) {
        int kk = i / NP;
        int c  = i - kk * NP;
        float w = 0.f;
        if (c < NOUT) w = W[kk * NOUT + c];
        ws[kk * NP + c] = w;
    }
    __syncthreads();

    unsigned long long acc2[8][NJ];
#pragma unroll
    for (int p = 0; p < 8; ++p)
#pragma unroll
        for (int j = 0; j < NJ; ++j) acc2[p][j] = 0ull;

#pragma unroll 4
    for (int k = 0; k < K; ++k) {
        const ulonglong2* pa = (const ulonglong2*)(xs + k * XSTR + ty * 16);
        ulonglong2 v0 = pa[0], v1 = pa[1], v2 = pa[2], v3 = pa[3];
        unsigned long long a[8] = {v0.x, v0.y, v1.x, v1.y, v2.x, v2.y, v3.x, v3.y};
#pragma unroll
        for (int j = 0; j < NJ; ++j) {
            float w = ws[k * NP + tx + 32 * j];
            unsigned long long wd = pack2(w, w);
#pragma unroll
            for (int p = 0; p < 8; ++p) ffma2(acc2[p][j], a[p], wd);
        }
    }

#pragma unroll
    for (int p = 0; p < 8; ++p) {
        int r0 = rbase + ty * 16 + 2 * p;
        int r1 = r0 + 1;
        float dv0 = 1.f, dv1 = 1.f;
        if (SCALE) {
            if (r0 < n) dv0 = dinv[r0];
            if (r1 < n) dv1 = dinv[r1];
        }
#pragma unroll
        for (int j = 0; j < NJ; ++j) {
            int c = tx + 32 * j;
            float2 v = unpack2(acc2[p][j]);
            if (OUTH) {
                if (r0 < n) outh[(size_t)r0 * OUTS + c] = __float2half(v.x * dv0);
                if (r1 < n) outh[(size_t)r1 * OUTS + c] = __float2half(v.y * dv1);
            } else if (c < NOUT) {
                float b = BIAS ? bias[c] : 0.f;
                if (r0 < n) outf[(size_t)r0 * OUTS + c] = v.x * dv0 + b;
                if (r1 < n) outf[(size_t)r1 * OUTS + c] = v.y * dv1 + b;
            }
        }
    }
}

// ---------------- mega kernel: slot-CSR fill (grid-stride) + layer-1 GEMM ------
__global__ void __launch_bounds__(256) mega1_kernel(const int* __restrict__ src,
                                                    const int* __restrict__ dst,
                                                    int e,
                                                    const float* __restrict__ x,
                                                    const float* __restrict__ W1,
                                                    __half* __restrict__ outh, int n) {
    extern __shared__ float smem[];
    if (blockIdx.x < FILLB) {
        const int nchunk = e >> 2;
        for (int c = blockIdx.x * 256 + threadIdx.x; c < nchunk; c += FILLB * 256) {
            int i = c * 4;
            int4 d4 = *(const int4*)(dst + i);
            int4 s4 = *(const int4*)(src + i);
            int p0 = atomicAdd(&g_cnt[d4.x], 1);
            int p1 = atomicAdd(&g_cnt[d4.y], 1);
            int p2 = atomicAdd(&g_cnt[d4.z], 1);
            int p3 = atomicAdd(&g_cnt[d4.w], 1);
            if (p0 < CAP) g_col[d4.x * CAP + p0] = s4.x;
            if (p1 < CAP) g_col[d4.y * CAP + p1] = s4.y;
            if (p2 < CAP) g_col[d4.z * CAP + p2] = s4.z;
            if (p3 < CAP) g_col[d4.w * CAP + p3] = s4.w;
        }
        if (blockIdx.x == 0 && threadIdx.x == 0) {
            for (int i = e & ~3; i < e; ++i) {
                int d = dst[i];
                int p = atomicAdd(&g_cnt[d], 1);
                if (p < CAP) g_col[d * CAP + p] = src[i];
            }
        }
        return;
    }
    gemm_body<F_IN, F_HID, 128, F_IN, PADH, false, false, true>(
        blockIdx.x - FILLB, x, W1, nullptr, nullptr, nullptr, outh, n, smem);
}

// ---------------- standalone GEMM ----------------
template<int K, int NOUT, int NP, int INS, int OUTS, bool SCALE, bool BIAS, bool OUTH>
__global__ void __launch_bounds__(256) gemm_kernel(const float* __restrict__ in,
                                                   const float* __restrict__ W,
                                                   const float* __restrict__ bias,
                                                   const float* __restrict__ dinv,
                                                   float* __restrict__ outf,
                                                   __half* __restrict__ outh, int n) {
    extern __shared__ float smem[];
    gemm_body<K, NOUT, NP, INS, OUTS, SCALE, BIAS, OUTH>(
        blockIdx.x, in, W, bias, dinv, outf, outh, n, smem);
}

__global__ void dinv_kernel(int n) {
    int i = blockIdx.x * blockDim.x + threadIdx.x;
    if (i < n) g_dinv[i] = rsqrtf((float)(g_cnt[i] + 1));   // +1 self loop
}

// ---------------- half-warp-per-node fp16 gather (layer 1, per-src scaling) ----
__global__ void __launch_bounds__(256) agg100_kernel(const __half* __restrict__ A,
                                                     const float* __restrict__ dinv,
                                                     const float* __restrict__ bias,
                                                     float* __restrict__ out, int n) {
    const int gwarp = (blockIdx.x * blockDim.x + threadIdx.x) >> 5;
    const int lane  = threadIdx.x & 31;
    const int node  = gwarp * 2 + (lane >> 4);
    const int sub   = lane & 15;                  // 16B chunk index (8 halves)
    if (node >= n) return;
    const uint4* __restrict__ base = (const uint4*)A;   // 16 uint4 per row
    const size_t rowoff = (size_t)node * 16;

    const float dvd = dinv[node];
    float acc[8] = {0.f, 0.f, 0.f, 0.f, 0.f, 0.f, 0.f, 0.f};
    h8_fma(base[rowoff + sub], dvd, acc);         // self loop term

    int deg = g_cnt[node]; if (deg > CAP) deg = CAP;
    const int4* __restrict__ colp = (const int4*)(g_col + node * CAP);
    const int nb4 = deg >> 2;
    for (int b = 0; b < nb4; ++b) {
        int4 i0 = colp[b];
        float d0 = dinv[i0.x], d1 = dinv[i0.y], d2 = dinv[i0.z], d3 = dinv[i0.w];
        uint4 v0 = base[(size_t)i0.x * 16 + sub];
        uint4 v1 = base[(size_t)i0.y * 16 + sub];
        uint4 v2 = base[(size_t)i0.z * 16 + sub];
        uint4 v3 = base[(size_t)i0.w * 16 + sub];
        h8_fma(v0, d0, acc); h8_fma(v1, d1, acc);
        h8_fma(v2, d2, acc); h8_fma(v3, d3, acc);
    }
    for (int e = nb4 * 4; e < deg; ++e) {
        int s = g_col[node * CAP + e];
        h8_fma(base[(size_t)s * 16 + sub], dinv[s], acc);
    }
    const int c0 = sub * 8;
    float* op = out + (size_t)node * F_HID + c0;
#pragma unroll
    for (int q = 0; q < 8; ++q) {
        int c = c0 + q;
        if (c < F_HID)
            op[q] = fmaxf(fmaf(acc[q], dvd, bias[c]), 0.f);
    }
}

// ---------------- quarter-warp-per-node fp16 gather (layer 2, pre-scaled rows) --
__global__ void __launch_bounds__(256) agg64_kernel(const __half* __restrict__ A,
                                                    const float* __restrict__ dinv,
                                                    const float* __restrict__ bias,
                                                    float* __restrict__ out, int n) {
    const int gwarp = (blockIdx.x * blockDim.x + threadIdx.x) >> 5;
    const int lane  = threadIdx.x & 31;
    const int node  = gwarp * 4 + (lane >> 3);
    const int sub   = lane & 7;                   // 16B chunk (8 halves)
    if (node >= n) return;
    const uint4* __restrict__ base = (const uint4*)A;   // 8 uint4 per row
    const size_t rowoff = (size_t)node * 8;

    float acc[8] = {0.f, 0.f, 0.f, 0.f, 0.f, 0.f, 0.f, 0.f};
    h8_add(base[rowoff + sub], acc);              // self loop term (pre-scaled)

    int deg = g_cnt[node]; if (deg > CAP) deg = CAP;
    const int4* __restrict__ colp = (const int4*)(g_col + node * CAP);
    const int nb4 = deg >> 2;
    for (int b = 0; b < nb4; ++b) {
        int4 i0 = colp[b];
        uint4 v0 = base[(size_t)i0.x * 8 + sub];
        uint4 v1 = base[(size_t)i0.y * 8 + sub];
        uint4 v2 = base[(size_t)i0.z * 8 + sub];
        uint4 v3 = base[(size_t)i0.w * 8 + sub];
        h8_add(v0, acc); h8_add(v1, acc); h8_add(v2, acc); h8_add(v3, acc);
    }
    for (int e = nb4 * 4; e < deg; ++e) {
        int s = g_col[node * CAP + e];
        h8_add(base[(size_t)s * 8 + sub], acc);
    }
    const float dv = dinv[node];
    const int c0 = sub * 8;
    float* op = out + (size_t)node * F_EMB + c0;
    float4 r0, r1;
    r0.x = fmaxf(fmaf(acc[0], dv, bias[c0 + 0]), 0.f);
    r0.y = fmaxf(fmaf(acc[1], dv, bias[c0 + 1]), 0.f);
    r0.z = fmaxf(fmaf(acc[2], dv, bias[c0 + 2]), 0.f);
    r0.w = fmaxf(fmaf(acc[3], dv, bias[c0 + 3]), 0.f);
    r1.x = fmaxf(fmaf(acc[4], dv, bias[c0 + 4]), 0.f);
    r1.y = fmaxf(fmaf(acc[5], dv, bias[c0 + 5]), 0.f);
    r1.z = fmaxf(fmaf(acc[6], dv, bias[c0 + 6]), 0.f);
    r1.w = fmaxf(fmaf(acc[7], dv, bias[c0 + 7]), 0.f);
    *(float4*)(op + 0) = r0;
    *(float4*)(op + 4) = r1;
}

// ---------------- host launcher ----------------
extern "C" void kernel_launch(void* const* d_in, const int* in_sizes, int n_in,
                              void* d_out, int out_size) {
    const float* x    = (const float*)d_in[0];
    const int*   eidx = (const int*)d_in[1];
    const float* W1   = (const float*)d_in[2];
    const float* b1   = (const float*)d_in[3];
    const float* W2   = (const float*)d_in[4];
    const float* b2   = (const float*)d_in[5];
    const float* Wc   = (const float*)d_in[6];
    const float* bc   = (const float*)d_in[7];
    float* out = (float*)d_out;

    const int n = in_sizes[0] / F_IN;       // 50000
    const int e = in_sizes[1] / 2;          // 800000
    const int* src = eidx;
    const int* dst = eidx + e;

    // Device symbols must be resolved to device addresses before being passed
    // as kernel arguments (host shadow is ATS-dereferenceable on GB300 -> zeros).
    __half* gAh1; cudaGetSymbolAddress((void**)&gAh1, g_Ah1);
    __half* gAh2; cudaGetSymbolAddress((void**)&gAh2, g_Ah2);
    float*  gB1;  cudaGetSymbolAddress((void**)&gB1,  g_B1);
    float*  gB2;  cudaGetSymbolAddress((void**)&gB2,  g_B2);
    float*  gDinv;cudaGetSymbolAddress((void**)&gDinv,g_dinv);
    int*    gCnt; cudaGetSymbolAddress((void**)&gCnt, g_cnt);

    // dynamic smem sizes (full-K staging)
    const int SM1 = (F_IN * XSTR + F_IN * 128) * 4;    // 104,000 B (mega/gemm1)
    const int SM2 = (F_HID * XSTR + F_HID * 64) * 4;   //  78,400 B
    const int SM3 = (F_EMB * XSTR + F_EMB * 64) * 4;   //  50,176 B
    cudaFuncSetAttribute(mega1_kernel,
                         cudaFuncAttributeMaxDynamicSharedMemorySize, SM1);
    cudaFuncSetAttribute(gemm_kernel<F_HID, F_EMB, 64, F_HID, F_EMB, true, false, true>,
                         cudaFuncAttributeMaxDynamicSharedMemorySize, SM2);
    cudaFuncSetAttribute(gemm_kernel<F_EMB, N_CLS, 64, F_EMB, N_CLS, false, true, false>,
                         cudaFuncAttributeMaxDynamicSharedMemorySize, SM3);

    const int TB = 256;
    const int gemm_blocks   = (n + 127) / 128;           // 391
    const int agg100_blocks = (n + 15) / 16;             // 2 nodes per warp
    const int agg64_blocks  = (n + 31) / 32;             // 4 nodes per warp

    // cursor zero, then fused {fill + gemm1(unscaled fp16)}
    cudaMemsetAsync(gCnt, 0, n * sizeof(int));
    mega1_kernel<<<FILLB + gemm_blocks, 256, SM1>>>(src, dst, e, x, W1, gAh1, n);
    dinv_kernel<<<(n + TB - 1) / TB, TB>>>(n);

    // layer 1 agg: per-src dinv scaling at gather
    agg100_kernel<<<agg100_blocks, 256>>>(gAh1, gDinv, b1, gB1, n);

    // layer 2: Ah2 = fp16( dinv * (B1 @ W2) ), one 128B line per row
    gemm_kernel<F_HID, F_EMB, 64, F_HID, F_EMB, true, false, true>
        <<<gemm_blocks, 256, SM2>>>(gB1, W2, nullptr, gDinv, nullptr, gAh2, n);
    agg64_kernel<<<agg64_blocks, 256>>>(gAh2, gDinv, b2, gB2, n);

    // classifier: out = B2 @ Wc + bc   (fp32)
    gemm_kernel<F_EMB, N_CLS, 64, F_EMB, N_CLS, false, true, false>
        <<<gemm_blocks, 256, SM3>>>(gB2, Wc, bc, nullptr, out, nullptr, n);
}

// round 16
// speedup vs baseline: 1.0044x; 1.0044x over previous
#include <cuda_runtime.h>
#include <cuda_fp16.h>

// Problem constants (fixed by the dataset)
#define F_IN 100
#define F_HID 100
#define F_EMB 64
#define N_CLS 40
#define NN   50000
#define EE   800000
#define CAP  96        // fixed slots per node; P(deg>=96) ~ 0 for Poisson(16)
#define PADH 128       // padded fp16 row stride for 100-wide activations (256B)
#define FILLB 296      // fill blocks fused into mega kernel (2 per SM)

// ---------------- scratch (no allocations allowed) ----------------
__device__ __half g_Ah1[NN * PADH];    // layer1 lin output, fp16 UNSCALED, padded
__device__ __half g_Ah2[NN * F_EMB];   // layer2 lin output, fp16, dinv-scaled (128B rows)
__device__ float  g_B1[NN * F_HID];    // layer1 agg output (fp32, stride 100)
__device__ float  g_B2[NN * F_EMB];    // layer2 agg output (fp32, stride 64)
__device__ int    g_cnt[NN];           // cursor -> degree
__device__ int    g_col[NN * CAP];     // slot CSR (CAP multiple of 4 -> int4 aligned)
__device__ float  g_dinv[NN];

// ---------------- f32x2 packed helpers (sm_103a) ----------------
__device__ __forceinline__ unsigned long long pack2(float lo, float hi) {
    unsigned long long r;
    asm("mov.b64 %0, {%1, %2};" : "=l"(r) : "f"(lo), "f"(hi));
    return r;
}
__device__ __forceinline__ void ffma2(unsigned long long& d,
                                      unsigned long long a,
                                      unsigned long long b) {
    asm("fma.rn.f32x2 %0, %1, %2, %3;" : "=l"(d) : "l"(a), "l"(b), "l"(d));
}
__device__ __forceinline__ float2 unpack2(unsigned long long v) {
    float lo, hi;
    asm("mov.b64 {%0, %1}, %2;" : "=f"(lo), "=f"(hi) : "l"(v));
    return make_float2(lo, hi);
}

// 8 packed halves (uint4) -> fp32, fused multiply-add into acc[8] with scale dv
__device__ __forceinline__ void h8_fma(uint4 v, float dv, float* acc) {
    float2 f0 = __half22float2(*(const __half2*)&v.x);
    float2 f1 = __half22float2(*(const __half2*)&v.y);
    float2 f2 = __half22float2(*(const __half2*)&v.z);
    float2 f3 = __half22float2(*(const __half2*)&v.w);
    acc[0] = fmaf(f0.x, dv, acc[0]); acc[1] = fmaf(f0.y, dv, acc[1]);
    acc[2] = fmaf(f1.x, dv, acc[2]); acc[3] = fmaf(f1.y, dv, acc[3]);
    acc[4] = fmaf(f2.x, dv, acc[4]); acc[5] = fmaf(f2.y, dv, acc[5]);
    acc[6] = fmaf(f3.x, dv, acc[6]); acc[7] = fmaf(f3.y, dv, acc[7]);
}
__device__ __forceinline__ void h8_add(uint4 v, float* acc) { h8_fma(v, 1.0f, acc); }

// ---------------- chunked GEMM body, BM=64, 8 rows/warp, dup-W smem ----------
// out[n, * (stride OUTS)] = in[n, K (stride INS)] @ W[K, NOUT]
// BK divides K exactly (no wasted k-steps). W staged PRE-DUPLICATED as {w,w}
// u64 so the inner loop is: 2x LDS.128 (a rows) + NJ x LDS.64 (w) + 8*NJ FFMA2.
template<int K, int BK, int NOUT, int NP, int INS, int OUTS,
         bool SCALE, bool BIAS, bool OUTH>
__device__ __forceinline__ void gemm_body(int bx,
                                          const float* __restrict__ in,
                                          const float* __restrict__ W,
                                          const float* __restrict__ bias,
                                          const float* __restrict__ dinv,
                                          float* __restrict__ outf,
                                          __half* __restrict__ outh, int n,
                                          float* smem) {
    constexpr int BM = 64, NJ = NP / 32, XS = BM + 4;   // XS=68 floats (272B, 16B-mult)
    constexpr int CV4 = BK / 4;                         // float4 per row per chunk
    static_assert(K % BK == 0 && BK % 4 == 0, "BK must divide K, mult of 4");
    float* xs = smem;                                   // [BK][XS] transposed
    unsigned long long* ws2 =
        (unsigned long long*)(smem + BK * XS);          // [BK][NP] dup pairs
    const int tid = threadIdx.x;
    const int tx = tid & 31, wid = tid >> 5;            // 8 warps, 8 rows each
    const int rbase = bx * BM;
    const int wrow  = wid * 8;

    unsigned long long acc2[4][NJ];                     // 4 row-pairs x NJ cols
#pragma unroll
    for (int p = 0; p < 4; ++p)
#pragma unroll
        for (int j = 0; j < NJ; ++j) acc2[p][j] = 0ull;

    for (int kc = 0; kc < K; kc += BK) {
        // stage x chunk transposed: 64 rows x BK k-values
        for (int idx = tid; idx < BM * CV4; idx += 256) {
            int row = idx / CV4;
            int c4  = idx - row * CV4;
            int grow = rbase + row;
            float4 xv = make_float4(0.f, 0.f, 0.f, 0.f);
            if (grow < n)                                // kc+c4*4+3 < K by construction
                xv = *(const float4*)(in + (size_t)grow * INS + kc + c4 * 4);
            float* xp = xs + (c4 * 4) * XS + row;
            xp[0 * XS] = xv.x;
            xp[1 * XS] = xv.y;
            xp[2 * XS] = xv.z;
            xp[3 * XS] = xv.w;
        }
        // stage W chunk as duplicated {w,w} u64 (zero-padded cols)
        for (int i = tid; i < BK * NP; i += 256) {
            int kk = i / NP;
            int c  = i - kk * NP;
            float w = 0.f;
            if (c < NOUT) w = W[(kc + kk) * NOUT + c];
            ws2[kk * NP + c] = pack2(w, w);
        }
        __syncthreads();
#pragma unroll 4
        for (int k = 0; k < BK; ++k) {
            const ulonglong2* pa = (const ulonglong2*)(xs + k * XS + wrow);
            ulonglong2 a01 = pa[0], a23 = pa[1];
            unsigned long long a[4] = {a01.x, a01.y, a23.x, a23.y};
            const unsigned long long* wp = ws2 + k * NP + tx;
#pragma unroll
            for (int j = 0; j < NJ; ++j) {
                unsigned long long wd = wp[32 * j];
#pragma unroll
                for (int p = 0; p < 4; ++p) ffma2(acc2[p][j], a[p], wd);
            }
        }
        __syncthreads();
    }
    // epilogue: 4 row pairs
#pragma unroll
    for (int p = 0; p < 4; ++p) {
        int r0 = rbase + wrow + 2 * p;
        int r1 = r0 + 1;
        float dv0 = 1.f, dv1 = 1.f;
        if (SCALE) {
            if (r0 < n) dv0 = dinv[r0];
            if (r1 < n) dv1 = dinv[r1];
        }
#pragma unroll
        for (int j = 0; j < NJ; ++j) {
            int c = tx + 32 * j;
            float2 v = unpack2(acc2[p][j]);
            if (OUTH) {
                if (r0 < n) outh[(size_t)r0 * OUTS + c] = __float2half(v.x * dv0);
                if (r1 < n) outh[(size_t)r1 * OUTS + c] = __float2half(v.y * dv1);
            } else if (c < NOUT) {
                float b = BIAS ? bias[c] : 0.f;
                if (r0 < n) outf[(size_t)r0 * OUTS + c] = v.x * dv0 + b;
                if (r1 < n) outf[(size_t)r1 * OUTS + c] = v.y * dv1 + b;
            }
        }
    }
}

// ---------------- mega kernel: slot-CSR fill (grid-stride) + layer-1 GEMM ------
__global__ void __launch_bounds__(256) mega1_kernel(const int* __restrict__ src,
                                                    const int* __restrict__ dst,
                                                    int e,
                                                    const float* __restrict__ x,
                                                    const float* __restrict__ W1,
                                                    __half* __restrict__ outh, int n) {
    extern __shared__ float smem[];
    if (blockIdx.x < FILLB) {
        const int nchunk = e >> 2;
        for (int c = blockIdx.x * 256 + threadIdx.x; c < nchunk; c += FILLB * 256) {
            int i = c * 4;
            int4 d4 = *(const int4*)(dst + i);
            int4 s4 = *(const int4*)(src + i);
            int p0 = atomicAdd(&g_cnt[d4.x], 1);
            int p1 = atomicAdd(&g_cnt[d4.y], 1);
            int p2 = atomicAdd(&g_cnt[d4.z], 1);
            int p3 = atomicAdd(&g_cnt[d4.w], 1);
            if (p0 < CAP) g_col[d4.x * CAP + p0] = s4.x;
            if (p1 < CAP) g_col[d4.y * CAP + p1] = s4.y;
            if (p2 < CAP) g_col[d4.z * CAP + p2] = s4.z;
            if (p3 < CAP) g_col[d4.w * CAP + p3] = s4.w;
        }
        if (blockIdx.x == 0 && threadIdx.x == 0) {
            for (int i = e & ~3; i < e; ++i) {
                int d = dst[i];
                int p = atomicAdd(&g_cnt[d], 1);
                if (p < CAP) g_col[d * CAP + p] = src[i];
            }
        }
        return;
    }
    gemm_body<F_IN, 20, F_HID, 128, F_IN, PADH, false, false, true>(
        blockIdx.x - FILLB, x, W1, nullptr, nullptr, nullptr, outh, n, smem);
}

// ---------------- standalone GEMM ----------------
template<int K, int BK, int NOUT, int NP, int INS, int OUTS,
         bool SCALE, bool BIAS, bool OUTH>
__global__ void __launch_bounds__(256) gemm_kernel(const float* __restrict__ in,
                                                   const float* __restrict__ W,
                                                   const float* __restrict__ bias,
                                                   const float* __restrict__ dinv,
                                                   float* __restrict__ outf,
                                                   __half* __restrict__ outh, int n) {
    extern __shared__ float smem[];
    gemm_body<K, BK, NOUT, NP, INS, OUTS, SCALE, BIAS, OUTH>(
        blockIdx.x, in, W, bias, dinv, outf, outh, n, smem);
}

__global__ void dinv_kernel(int n) {
    int i = blockIdx.x * blockDim.x + threadIdx.x;
    if (i < n) g_dinv[i] = rsqrtf((float)(g_cnt[i] + 1));   // +1 self loop
}

// ---------------- half-warp-per-node fp16 gather (layer 1, per-src scaling) ----
__global__ void __launch_bounds__(256) agg100_kernel(const __half* __restrict__ A,
                                                     const float* __restrict__ dinv,
                                                     const float* __restrict__ bias,
                                                     float* __restrict__ out, int n) {
    const int gwarp = (blockIdx.x * blockDim.x + threadIdx.x) >> 5;
    const int lane  = threadIdx.x & 31;
    const int node  = gwarp * 2 + (lane >> 4);
    const int sub   = lane & 15;                  // 16B chunk index (8 halves)
    if (node >= n) return;
    const uint4* __restrict__ base = (const uint4*)A;   // 16 uint4 per row
    const size_t rowoff = (size_t)node * 16;

    const float dvd = dinv[node];
    float acc[8] = {0.f, 0.f, 0.f, 0.f, 0.f, 0.f, 0.f, 0.f};
    h8_fma(base[rowoff + sub], dvd, acc);         // self loop term

    int deg = g_cnt[node]; if (deg > CAP) deg = CAP;
    const int4* __restrict__ colp = (const int4*)(g_col + node * CAP);
    const int nb4 = deg >> 2;
    for (int b = 0; b < nb4; ++b) {
        int4 i0 = colp[b];
        float d0 = dinv[i0.x], d1 = dinv[i0.y], d2 = dinv[i0.z], d3 = dinv[i0.w];
        uint4 v0 = base[(size_t)i0.x * 16 + sub];
        uint4 v1 = base[(size_t)i0.y * 16 + sub];
        uint4 v2 = base[(size_t)i0.z * 16 + sub];
        uint4 v3 = base[(size_t)i0.w * 16 + sub];
        h8_fma(v0, d0, acc); h8_fma(v1, d1, acc);
        h8_fma(v2, d2, acc); h8_fma(v3, d3, acc);
    }
    for (int e = nb4 * 4; e < deg; ++e) {
        int s = g_col[node * CAP + e];
        h8_fma(base[(size_t)s * 16 + sub], dinv[s], acc);
    }
    const int c0 = sub * 8;
    float* op = out + (size_t)node * F_HID + c0;
#pragma unroll
    for (int q = 0; q < 8; ++q) {
        int c = c0 + q;
        if (c < F_HID)
            op[q] = fmaxf(fmaf(acc[q], dvd, bias[c]), 0.f);
    }
}

// ---------------- quarter-warp-per-node fp16 gather (layer 2, pre-scaled rows) --
__global__ void __launch_bounds__(256) agg64_kernel(const __half* __restrict__ A,
                                                    const float* __restrict__ dinv,
                                                    const float* __restrict__ bias,
                                                    float* __restrict__ out, int n) {
    const int gwarp = (blockIdx.x * blockDim.x + threadIdx.x) >> 5;
    const int lane  = threadIdx.x & 31;
    const int node  = gwarp * 4 + (lane >> 3);
    const int sub   = lane & 7;                   // 16B chunk (8 halves)
    if (node >= n) return;
    const uint4* __restrict__ base = (const uint4*)A;   // 8 uint4 per row
    const size_t rowoff = (size_t)node * 8;

    float acc[8] = {0.f, 0.f, 0.f, 0.f, 0.f, 0.f, 0.f, 0.f};
    h8_add(base[rowoff + sub], acc);              // self loop term (pre-scaled)

    int deg = g_cnt[node]; if (deg > CAP) deg = CAP;
    const int4* __restrict__ colp = (const int4*)(g_col + node * CAP);
    const int nb4 = deg >> 2;
    for (int b = 0; b < nb4; ++b) {
        int4 i0 = colp[b];
        uint4 v0 = base[(size_t)i0.x * 8 + sub];
        uint4 v1 = base[(size_t)i0.y * 8 + sub];
        uint4 v2 = base[(size_t)i0.z * 8 + sub];
        uint4 v3 = base[(size_t)i0.w * 8 + sub];
        h8_add(v0, acc); h8_add(v1, acc); h8_add(v2, acc); h8_add(v3, acc);
    }
    for (int e = nb4 * 4; e < deg; ++e) {
        int s = g_col[node * CAP + e];
        h8_add(base[(size_t)s * 8 + sub], acc);
    }
    const float dv = dinv[node];
    const int c0 = sub * 8;
    float* op = out + (size_t)node * F_EMB + c0;
    float4 r0, r1;
    r0.x = fmaxf(fmaf(acc[0], dv, bias[c0 + 0]), 0.f);
    r0.y = fmaxf(fmaf(acc[1], dv, bias[c0 + 1]), 0.f);
    r0.z = fmaxf(fmaf(acc[2], dv, bias[c0 + 2]), 0.f);
    r0.w = fmaxf(fmaf(acc[3], dv, bias[c0 + 3]), 0.f);
    r1.x = fmaxf(fmaf(acc[4], dv, bias[c0 + 4]), 0.f);
    r1.y = fmaxf(fmaf(acc[5], dv, bias[c0 + 5]), 0.f);
    r1.z = fmaxf(fmaf(acc[6], dv, bias[c0 + 6]), 0.f);
    r1.w = fmaxf(fmaf(acc[7], dv, bias[c0 + 7]), 0.f);
    *(float4*)(op + 0) = r0;
    *(float4*)(op + 4) = r1;
}

// ---------------- host launcher ----------------
extern "C" void kernel_launch(void* const* d_in, const int* in_sizes, int n_in,
                              void* d_out, int out_size) {
    const float* x    = (const float*)d_in[0];
    const int*   eidx = (const int*)d_in[1];
    const float* W1   = (const float*)d_in[2];
    const float* b1   = (const float*)d_in[3];
    const float* W2   = (const float*)d_in[4];
    const float* b2   = (const float*)d_in[5];
    const float* Wc   = (const float*)d_in[6];
    const float* bc   = (const float*)d_in[7];
    float* out = (float*)d_out;

    const int n = in_sizes[0] / F_IN;       // 50000
    const int e = in_sizes[1] / 2;          // 800000
    const int* src = eidx;
    const int* dst = eidx + e;

    // Device symbols must be resolved to device addresses before being passed
    // as kernel arguments (host shadow is ATS-dereferenceable on GB300 -> zeros).
    __half* gAh1; cudaGetSymbolAddress((void**)&gAh1, g_Ah1);
    __half* gAh2; cudaGetSymbolAddress((void**)&gAh2, g_Ah2);
    float*  gB1;  cudaGetSymbolAddress((void**)&gB1,  g_B1);
    float*  gB2;  cudaGetSymbolAddress((void**)&gB2,  g_B2);
    float*  gDinv;cudaGetSymbolAddress((void**)&gDinv,g_dinv);
    int*    gCnt; cudaGetSymbolAddress((void**)&gCnt, g_cnt);

    // dynamic smem per GEMM variant (xs chunk + duplicated-W chunk), all <48KB
    const int SM1 = (20 * 68) * 4 + 20 * 128 * 8;   // 25,920 B (gemm1 / mega)
    const int SM2 = (20 * 68) * 4 + 20 * 64 * 8;    // 15,680 B
    const int SM3 = (32 * 68) * 4 + 32 * 64 * 8;    // 25,088 B

    const int TB = 256;
    const int gemm_blocks   = (n + 63) / 64;             // 782  (BM=64)
    const int agg100_blocks = (n + 15) / 16;             // 2 nodes per warp
    const int agg64_blocks  = (n + 31) / 32;             // 4 nodes per warp

    // cursor zero, then fused {fill + gemm1(unscaled fp16)}
    cudaMemsetAsync(gCnt, 0, n * sizeof(int));
    mega1_kernel<<<FILLB + gemm_blocks, 256, SM1>>>(src, dst, e, x, W1, gAh1, n);
    dinv_kernel<<<(n + TB - 1) / TB, TB>>>(n);

    // layer 1 agg: per-src dinv scaling at gather
    agg100_kernel<<<agg100_blocks, 256>>>(gAh1, gDinv, b1, gB1, n);

    // layer 2: Ah2 = fp16( dinv * (B1 @ W2) ), one 128B line per row
    gemm_kernel<F_HID, 20, F_EMB, 64, F_HID, F_EMB, true, false, true>
        <<<gemm_blocks, 256, SM2>>>(gB1, W2, nullptr, gDinv, nullptr, gAh2, n);
    agg64_kernel<<<agg64_blocks, 256>>>(gAh2, gDinv, b2, gB2, n);

    // classifier: out = B2 @ Wc + bc   (fp32)
    gemm_kernel<F_EMB, 32, N_CLS, 64, F_EMB, N_CLS, false, true, false>
        <<<gemm_blocks, 256, SM3>>>(gB2, Wc, bc, nullptr, out, nullptr, n);
}

// round 17
// speedup vs baseline: 1.0881x; 1.0833x over previous
#include <cuda_runtime.h>
#include <cuda_fp16.h>

// Problem constants (fixed by the dataset)
#define F_IN 100
#define F_HID 100
#define F_EMB 64
#define N_CLS 40
#define NN   50000
#define EE   800000
#define CAP  96        // fixed slots per node; P(deg>=96) ~ 0 for Poisson(16)
#define PADH 128       // padded fp16 row stride for 100-wide activations (256B)
#define FILLB 296      // fill blocks fused into mega kernel

// ---------------- scratch (no allocations allowed) ----------------
__device__ __half g_Ah1[NN * PADH];    // layer1 lin output, fp16 UNSCALED, padded
__device__ __half g_Ah2[NN * F_EMB];   // layer2 lin output, fp16, dinv-scaled (128B rows)
__device__ float  g_B1[NN * F_HID];    // layer1 agg output (fp32, stride 100)
__device__ float  g_B2[NN * F_EMB];    // layer2 agg output (fp32, stride 64)
__device__ int    g_cnt[NN];           // cursor -> degree
__device__ int    g_col[NN * CAP];     // slot CSR (CAP multiple of 4 -> int4 aligned)
__device__ float  g_dinv[NN];

// ---------------- f32x2 packed helpers (sm_103a) ----------------
__device__ __forceinline__ unsigned long long pack2(float lo, float hi) {
    unsigned long long r;
    asm("mov.b64 %0, {%1, %2};" : "=l"(r) : "f"(lo), "f"(hi));
    return r;
}
__device__ __forceinline__ void ffma2(unsigned long long& d,
                                      unsigned long long a,
                                      unsigned long long b) {
    asm("fma.rn.f32x2 %0, %1, %2, %3;" : "=l"(d) : "l"(a), "l"(b), "l"(d));
}
__device__ __forceinline__ float2 unpack2(unsigned long long v) {
    float lo, hi;
    asm("mov.b64 {%0, %1}, %2;" : "=f"(lo), "=f"(hi) : "l"(v));
    return make_float2(lo, hi);
}

// 8 packed halves (uint4) -> fp32, fused multiply-add into acc[8] with scale dv
__device__ __forceinline__ void h8_fma(uint4 v, float dv, float* acc) {
    float2 f0 = __half22float2(*(const __half2*)&v.x);
    float2 f1 = __half22float2(*(const __half2*)&v.y);
    float2 f2 = __half22float2(*(const __half2*)&v.z);
    float2 f3 = __half22float2(*(const __half2*)&v.w);
    acc[0] = fmaf(f0.x, dv, acc[0]); acc[1] = fmaf(f0.y, dv, acc[1]);
    acc[2] = fmaf(f1.x, dv, acc[2]); acc[3] = fmaf(f1.y, dv, acc[3]);
    acc[4] = fmaf(f2.x, dv, acc[4]); acc[5] = fmaf(f2.y, dv, acc[5]);
    acc[6] = fmaf(f3.x, dv, acc[6]); acc[7] = fmaf(f3.y, dv, acc[7]);
}
__device__ __forceinline__ void h8_add(uint4 v, float* acc) { h8_fma(v, 1.0f, acc); }

// ---------------- HMMA m16n8k16 (fp16 in, fp32 accumulate) ----------------
__device__ __forceinline__ void mma16816(float* d,
                                         unsigned a0, unsigned a1, unsigned a2, unsigned a3,
                                         unsigned b0, unsigned b1) {
    asm volatile(
        "mma.sync.aligned.m16n8k16.row.col.f32.f16.f16.f32 "
        "{%0,%1,%2,%3}, {%4,%5,%6,%7}, {%8,%9}, {%0,%1,%2,%3};"
        : "+f"(d[0]), "+f"(d[1]), "+f"(d[2]), "+f"(d[3])
        : "r"(a0), "r"(a1), "r"(a2), "r"(a3), "r"(b0), "r"(b1));
}

// ---------------- tensor-core GEMM body (fp32 in -> fp16 out) ----------------
// outh[n, OUTS] = fp16( dinv?[row] * (in[n, K (stride INS)] @ W[K, NOUT]) )
// NPAD = OUTS (all output columns written; pad cols get exact zeros via W-pad).
// 128 threads = 4 warps; BM=64 (16 rows/warp). smem rows stride XSH=120 halves
// (conflict-free fragment loads); logical K padded to KT*16 <= 120 with zeros.
template<int K, int NOUT, int NPAD, int INS, int OUTS, bool SCALE>
__device__ __forceinline__ void hgemm_body(int bx,
                                           const float* __restrict__ in,
                                           const float* __restrict__ W,
                                           const float* __restrict__ dinv,
                                           __half* __restrict__ outh, int n,
                                           __half* hsm) {
    constexpr int BM = 64, XSH = 120, KT = (K + 15) / 16, NT = NPAD / 8;
    constexpr int CV4 = XSH / 4;                 // 30 4-half chunks per row
    static_assert(KT * 16 <= XSH, "K padding must fit stride");
    __half* As = hsm;                            // [BM][XSH]
    __half* Wt = hsm + BM * XSH;                 // [NPAD][XSH]  (n-major, k contiguous)
    const int tid  = threadIdx.x;
    const int lane = tid & 31, wid = tid >> 5;   // 4 warps
    const int rbase = bx * BM;

    // stage A: fp32 -> fp16, zero-pad k >= K
    for (int idx = tid; idx < BM * CV4; idx += 128) {
        int row = idx / CV4, c4 = idx - row * CV4;
        int grow = rbase + row;
        float4 xv = make_float4(0.f, 0.f, 0.f, 0.f);
        if (grow < n && c4 * 4 < K)              // K % 4 == 0 -> full float4 valid
            xv = *(const float4*)(in + (size_t)grow * INS + c4 * 4);
        __half2* dp = (__half2*)(As + row * XSH + c4 * 4);
        dp[0] = __floats2half2_rn(xv.x, xv.y);
        dp[1] = __floats2half2_rn(xv.z, xv.w);
    }
    // stage W transposed: Wt[nn][k], zero-pad nn >= NOUT and k >= K
    for (int idx = tid; idx < NPAD * CV4; idx += 128) {
        int nn = idx / CV4, c4 = idx - nn * CV4;
        float w[4] = {0.f, 0.f, 0.f, 0.f};
        if (nn < NOUT) {
#pragma unroll
            for (int j = 0; j < 4; ++j) {
                int k = c4 * 4 + j;
                if (k < K) w[j] = W[k * NOUT + nn];
            }
        }
        __half2* dp = (__half2*)(Wt + nn * XSH + c4 * 4);
        dp[0] = __floats2half2_rn(w[0], w[1]);
        dp[1] = __floats2half2_rn(w[2], w[3]);
    }
    __syncthreads();

    float acc[NT][4];
#pragma unroll
    for (int nt = 0; nt < NT; ++nt)
#pragma unroll
        for (int q = 0; q < 4; ++q) acc[nt][q] = 0.f;

    const int wrow  = wid * 16;
    const int arow  = wrow + (lane >> 2);        // a rows: arow, arow+8
    const int kcol0 = (lane & 3) * 2;            // fragment k-pair base
    const int brow  = (lane >> 2);               // b n-index within 8-tile

#pragma unroll
    for (int kt = 0; kt < KT; ++kt) {
        const __half* ap = As + arow * XSH + kt * 16 + kcol0;
        unsigned a0 = *(const unsigned*)(ap);
        unsigned a1 = *(const unsigned*)(ap + 8 * XSH);
        unsigned a2 = *(const unsigned*)(ap + 8);
        unsigned a3 = *(const unsigned*)(ap + 8 * XSH + 8);
        const __half* bp = Wt + brow * XSH + kt * 16 + kcol0;
#pragma unroll
        for (int nt = 0; nt < NT; ++nt) {
            unsigned b0 = *(const unsigned*)(bp + nt * 8 * XSH);
            unsigned b1 = *(const unsigned*)(bp + nt * 8 * XSH + 8);
            mma16816(acc[nt], a0, a1, a2, a3, b0, b1);
        }
    }

    // epilogue: rows r0 = rbase+wrow+lane/4, r1 = r0+8; cols nt*8 + (lane%4)*2
    const int r0 = rbase + wrow + (lane >> 2);
    const int r1 = r0 + 8;
    float dv0 = 1.f, dv1 = 1.f;
    if (SCALE) {
        if (r0 < n) dv0 = dinv[r0];
        if (r1 < n) dv1 = dinv[r1];
    }
#pragma unroll
    for (int nt = 0; nt < NT; ++nt) {
        int c = nt * 8 + kcol0;
        if (r0 < n)
            *(__half2*)(outh + (size_t)r0 * OUTS + c) =
                __floats2half2_rn(acc[nt][0] * dv0, acc[nt][1] * dv0);
        if (r1 < n)
            *(__half2*)(outh + (size_t)r1 * OUTS + c) =
                __floats2half2_rn(acc[nt][2] * dv1, acc[nt][3] * dv1);
    }
}

// ---------------- mega kernel: slot-CSR fill (grid-stride) + layer-1 HMMA GEMM --
__global__ void __launch_bounds__(128) mega1_kernel(const int* __restrict__ src,
                                                    const int* __restrict__ dst,
                                                    int e,
                                                    const float* __restrict__ x,
                                                    const float* __restrict__ W1,
                                                    __half* __restrict__ outh, int n) {
    extern __shared__ __half hsm[];
    if (blockIdx.x < FILLB) {
        const int nchunk = e >> 2;
        for (int c = blockIdx.x * 128 + threadIdx.x; c < nchunk; c += FILLB * 128) {
            int i = c * 4;
            int4 d4 = *(const int4*)(dst + i);
            int4 s4 = *(const int4*)(src + i);
            int p0 = atomicAdd(&g_cnt[d4.x], 1);
            int p1 = atomicAdd(&g_cnt[d4.y], 1);
            int p2 = atomicAdd(&g_cnt[d4.z], 1);
            int p3 = atomicAdd(&g_cnt[d4.w], 1);
            if (p0 < CAP) g_col[d4.x * CAP + p0] = s4.x;
            if (p1 < CAP) g_col[d4.y * CAP + p1] = s4.y;
            if (p2 < CAP) g_col[d4.z * CAP + p2] = s4.z;
            if (p3 < CAP) g_col[d4.w * CAP + p3] = s4.w;
        }
        if (blockIdx.x == 0 && threadIdx.x == 0) {
            for (int i = e & ~3; i < e; ++i) {
                int d = dst[i];
                int p = atomicAdd(&g_cnt[d], 1);
                if (p < CAP) g_col[d * CAP + p] = src[i];
            }
        }
        return;
    }
    // gemm1: x[n,100] @ W1[100,100] -> fp16 unscaled, OUTS=NPAD=128 (pad cols zero)
    hgemm_body<F_IN, F_HID, PADH, F_IN, PADH, false>(
        blockIdx.x - FILLB, x, W1, nullptr, outh, n, hsm);
}

// ---------------- standalone HMMA GEMM (layer 2) ----------------
template<int K, int NOUT, int NPAD, int INS, int OUTS, bool SCALE>
__global__ void __launch_bounds__(128) hgemm_kernel(const float* __restrict__ in,
                                                    const float* __restrict__ W,
                                                    const float* __restrict__ dinv,
                                                    __half* __restrict__ outh, int n) {
    extern __shared__ __half hsm[];
    hgemm_body<K, NOUT, NPAD, INS, OUTS, SCALE>(blockIdx.x, in, W, dinv, outh, n, hsm);
}

// ---------------- chunked f32x2 GEMM (classifier, fp32 output) ----------------
template<int K, int BK, int NOUT, int NP, int INS, int OUTS, bool BIAS>
__global__ void __launch_bounds__(256) gemm_kernel(const float* __restrict__ in,
                                                   const float* __restrict__ W,
                                                   const float* __restrict__ bias,
                                                   float* __restrict__ outf, int n) {
    constexpr int BM = 64, NJ = NP / 32, XS = BM + 4;
    constexpr int CV4 = BK / 4;
    extern __shared__ float smem[];
    float* xs = smem;
    unsigned long long* ws2 = (unsigned long long*)(smem + BK * XS);
    const int tid = threadIdx.x;
    const int tx = tid & 31, wid = tid >> 5;
    const int rbase = blockIdx.x * BM;
    const int wrow  = wid * 8;

    unsigned long long acc2[4][NJ];
#pragma unroll
    for (int p = 0; p < 4; ++p)
#pragma unroll
        for (int j = 0; j < NJ; ++j) acc2[p][j] = 0ull;

    for (int kc = 0; kc < K; kc += BK) {
        for (int idx = tid; idx < BM * CV4; idx += 256) {
            int row = idx / CV4;
            int c4  = idx - row * CV4;
            int grow = rbase + row;
            float4 xv = make_float4(0.f, 0.f, 0.f, 0.f);
            if (grow < n)
                xv = *(const float4*)(in + (size_t)grow * INS + kc + c4 * 4);
            float* xp = xs + (c4 * 4) * XS + row;
            xp[0 * XS] = xv.x;
            xp[1 * XS] = xv.y;
            xp[2 * XS] = xv.z;
            xp[3 * XS] = xv.w;
        }
        for (int i = tid; i < BK * NP; i += 256) {
            int kk = i / NP;
            int c  = i - kk * NP;
            float w = 0.f;
            if (c < NOUT) w = W[(kc + kk) * NOUT + c];
            ws2[kk * NP + c] = pack2(w, w);
        }
        __syncthreads();
#pragma unroll 4
        for (int k = 0; k < BK; ++k) {
            const ulonglong2* pa = (const ulonglong2*)(xs + k * XS + wrow);
            ulonglong2 a01 = pa[0], a23 = pa[1];
            unsigned long long a[4] = {a01.x, a01.y, a23.x, a23.y};
            const unsigned long long* wp = ws2 + k * NP + tx;
#pragma unroll
            for (int j = 0; j < NJ; ++j) {
                unsigned long long wd = wp[32 * j];
#pragma unroll
                for (int p = 0; p < 4; ++p) ffma2(acc2[p][j], a[p], wd);
            }
        }
        __syncthreads();
    }
#pragma unroll
    for (int p = 0; p < 4; ++p) {
        int r0 = rbase + wrow + 2 * p;
        int r1 = r0 + 1;
#pragma unroll
        for (int j = 0; j < NJ; ++j) {
            int c = tx + 32 * j;
            float2 v = unpack2(acc2[p][j]);
            if (c < NOUT) {
                float b = BIAS ? bias[c] : 0.f;
                if (r0 < n) outf[(size_t)r0 * OUTS + c] = v.x + b;
                if (r1 < n) outf[(size_t)r1 * OUTS + c] = v.y + b;
            }
        }
    }
}

__global__ void dinv_kernel(int n) {
    int i = blockIdx.x * blockDim.x + threadIdx.x;
    if (i < n) g_dinv[i] = rsqrtf((float)(g_cnt[i] + 1));   // +1 self loop
}

// ---------------- half-warp-per-node fp16 gather (layer 1, per-src scaling) ----
__global__ void __launch_bounds__(256) agg100_kernel(const __half* __restrict__ A,
                                                     const float* __restrict__ dinv,
                                                     const float* __restrict__ bias,
                                                     float* __restrict__ out, int n) {
    const int gwarp = (blockIdx.x * blockDim.x + threadIdx.x) >> 5;
    const int lane  = threadIdx.x & 31;
    const int node  = gwarp * 2 + (lane >> 4);
    const int sub   = lane & 15;                  // 16B chunk index (8 halves)
    if (node >= n) return;
    const uint4* __restrict__ base = (const uint4*)A;   // 16 uint4 per row
    const size_t rowoff = (size_t)node * 16;

    const float dvd = dinv[node];
    float acc[8] = {0.f, 0.f, 0.f, 0.f, 0.f, 0.f, 0.f, 0.f};
    h8_fma(base[rowoff + sub], dvd, acc);         // self loop term

    int deg = g_cnt[node]; if (deg > CAP) deg = CAP;
    const int4* __restrict__ colp = (const int4*)(g_col + node * CAP);
    const int nb4 = deg >> 2;
    for (int b = 0; b < nb4; ++b) {
        int4 i0 = colp[b];
        float d0 = dinv[i0.x], d1 = dinv[i0.y], d2 = dinv[i0.z], d3 = dinv[i0.w];
        uint4 v0 = base[(size_t)i0.x * 16 + sub];
        uint4 v1 = base[(size_t)i0.y * 16 + sub];
        uint4 v2 = base[(size_t)i0.z * 16 + sub];
        uint4 v3 = base[(size_t)i0.w * 16 + sub];
        h8_fma(v0, d0, acc); h8_fma(v1, d1, acc);
        h8_fma(v2, d2, acc); h8_fma(v3, d3, acc);
    }
    for (int e = nb4 * 4; e < deg; ++e) {
        int s = g_col[node * CAP + e];
        h8_fma(base[(size_t)s * 16 + sub], dinv[s], acc);
    }
    const int c0 = sub * 8;
    float* op = out + (size_t)node * F_HID + c0;
#pragma unroll
    for (int q = 0; q < 8; ++q) {
        int c = c0 + q;
        if (c < F_HID)
            op[q] = fmaxf(fmaf(acc[q], dvd, bias[c]), 0.f);
    }
}

// ---------------- quarter-warp-per-node fp16 gather (layer 2, pre-scaled rows) --
__global__ void __launch_bounds__(256) agg64_kernel(const __half* __restrict__ A,
                                                    const float* __restrict__ dinv,
                                                    const float* __restrict__ bias,
                                                    float* __restrict__ out, int n) {
    const int gwarp = (blockIdx.x * blockDim.x + threadIdx.x) >> 5;
    const int lane  = threadIdx.x & 31;
    const int node  = gwarp * 4 + (lane >> 3);
    const int sub   = lane & 7;                   // 16B chunk (8 halves)
    if (node >= n) return;
    const uint4* __restrict__ base = (const uint4*)A;   // 8 uint4 per row
    const size_t rowoff = (size_t)node * 8;

    float acc[8] = {0.f, 0.f, 0.f, 0.f, 0.f, 0.f, 0.f, 0.f};
    h8_add(base[rowoff + sub], acc);              // self loop term (pre-scaled)

    int deg = g_cnt[node]; if (deg > CAP) deg = CAP;
    const int4* __restrict__ colp = (const int4*)(g_col + node * CAP);
    const int nb4 = deg >> 2;
    for (int b = 0; b < nb4; ++b) {
        int4 i0 = colp[b];
        uint4 v0 = base[(size_t)i0.x * 8 + sub];
        uint4 v1 = base[(size_t)i0.y * 8 + sub];
        uint4 v2 = base[(size_t)i0.z * 8 + sub];
        uint4 v3 = base[(size_t)i0.w * 8 + sub];
        h8_add(v0, acc); h8_add(v1, acc); h8_add(v2, acc); h8_add(v3, acc);
    }
    for (int e = nb4 * 4; e < deg; ++e) {
        int s = g_col[node * CAP + e];
        h8_add(base[(size_t)s * 8 + sub], acc);
    }
    const float dv = dinv[node];
    const int c0 = sub * 8;
    float* op = out + (size_t)node * F_EMB + c0;
    float4 r0, r1;
    r0.x = fmaxf(fmaf(acc[0], dv, bias[c0 + 0]), 0.f);
    r0.y = fmaxf(fmaf(acc[1], dv, bias[c0 + 1]), 0.f);
    r0.z = fmaxf(fmaf(acc[2], dv, bias[c0 + 2]), 0.f);
    r0.w = fmaxf(fmaf(acc[3], dv, bias[c0 + 3]), 0.f);
    r1.x = fmaxf(fmaf(acc[4], dv, bias[c0 + 4]), 0.f);
    r1.y = fmaxf(fmaf(acc[5], dv, bias[c0 + 5]), 0.f);
    r1.z = fmaxf(fmaf(acc[6], dv, bias[c0 + 6]), 0.f);
    r1.w = fmaxf(fmaf(acc[7], dv, bias[c0 + 7]), 0.f);
    *(float4*)(op + 0) = r0;
    *(float4*)(op + 4) = r1;
}

// ---------------- host launcher ----------------
extern "C" void kernel_launch(void* const* d_in, const int* in_sizes, int n_in,
                              void* d_out, int out_size) {
    const float* x    = (const float*)d_in[0];
    const int*   eidx = (const int*)d_in[1];
    const float* W1   = (const float*)d_in[2];
    const float* b1   = (const float*)d_in[3];
    const float* W2   = (const float*)d_in[4];
    const float* b2   = (const float*)d_in[5];
    const float* Wc   = (const float*)d_in[6];
    const float* bc   = (const float*)d_in[7];
    float* out = (float*)d_out;

    const int n = in_sizes[0] / F_IN;       // 50000
    const int e = in_sizes[1] / 2;          // 800000
    const int* src = eidx;
    const int* dst = eidx + e;

    // Device symbols must be resolved to device addresses before being passed
    // as kernel arguments (host shadow is ATS-dereferenceable on GB300 -> zeros).
    __half* gAh1; cudaGetSymbolAddress((void**)&gAh1, g_Ah1);
    __half* gAh2; cudaGetSymbolAddress((void**)&gAh2, g_Ah2);
    float*  gB1;  cudaGetSymbolAddress((void**)&gB1,  g_B1);
    float*  gB2;  cudaGetSymbolAddress((void**)&gB2,  g_B2);
    float*  gDinv;cudaGetSymbolAddress((void**)&gDinv,g_dinv);
    int*    gCnt; cudaGetSymbolAddress((void**)&gCnt, g_cnt);

    // smem: hgemm1 (As 64 + Wt 128 rows)*120 halves = 46,080 B (<48K)
    //       hgemm2 (64+64)*120*2                    = 30,720 B
    //       gemm3  (32*68)*4 + 32*64*8              = 25,088 B
    const int HSM1 = (64 + PADH) * 120 * 2;
    const int HSM2 = (64 + F_EMB) * 120 * 2;
    const int SM3  = (32 * 68) * 4 + 32 * 64 * 8;

    const int TB = 256;
    const int gemm_blocks   = (n + 63) / 64;             // 782 (BM=64)
    const int agg100_blocks = (n + 15) / 16;             // 2 nodes per warp
    const int agg64_blocks  = (n + 31) / 32;             // 4 nodes per warp

    // cursor zero, then fused {fill + hgemm1(unscaled fp16)}
    cudaMemsetAsync(gCnt, 0, n * sizeof(int));
    mega1_kernel<<<FILLB + gemm_blocks, 128, HSM1>>>(src, dst, e, x, W1, gAh1, n);
    dinv_kernel<<<(n + TB - 1) / TB, TB>>>(n);

    // layer 1 agg: per-src dinv scaling at gather
    agg100_kernel<<<agg100_blocks, 256>>>(gAh1, gDinv, b1, gB1, n);

    // layer 2: Ah2 = fp16( dinv * (B1 @ W2) ), one 128B line per row  (HMMA)
    hgemm_kernel<F_HID, F_EMB, F_EMB, F_HID, F_EMB, true>
        <<<gemm_blocks, 128, HSM2>>>(gB1, W2, gDinv, gAh2, n);
    agg64_kernel<<<agg64_blocks, 256>>>(gAh2, gDinv, b2, gB2, n);

    // classifier: out = B2 @ Wc + bc   (fp32 f32x2 path for final precision)
    gemm_kernel<F_EMB, 32, N_CLS, 64, F_EMB, N_CLS, true>
        <<<gemm_blocks, 256, SM3>>>(gB2, Wc, bc, out, n);
}